// round 7
// baseline (speedup 1.0000x reference)
#include <cuda_runtime.h>
#include <cuda_fp16.h>

// Channel-last fp16 copies of all 4 img tensors.
// Half-element offsets: s512: 0 | s256: 67,108,864 | s128: 83,886,080 |
// s64: 88,080,384. Total 89,128,960 halfs.
__device__ __half g_timg[89128960];

// Per-scale block counts (256 threads, 2 threads/pixel):
//   s512: 32768 (2048/batch) | s256: 8192 | s128: 2048 | s64: 512

// ---------------------------------------------------------------------------
// Transpose [B,C,H,W] fp32 -> [B,H,W,C] fp16 (no smem). Thread t ->
// (pixel p=t>>1, channel group g=t&1): 8 strided coalesced LDG.32 (streaming),
// one coalesced STG.128 (default policy -> stays L2-resident for the gather).
// ---------------------------------------------------------------------------
template <unsigned LG>
__device__ __forceinline__ void do_transpose(const float* __restrict__ img,
                                             __half* __restrict__ timg,
                                             unsigned bx) {
    const unsigned t  = bx * 256u + threadIdx.x;
    const unsigned g  = t & 1u;
    const unsigned p  = t >> 1;
    constexpr unsigned HW = 1u << (2u * LG);
    const unsigned b  = p >> (2u * LG);

    const float* src = img + (size_t)p + (size_t)(b * 15u + g * 8u) * HW;
    float v[8];
#pragma unroll
    for (int k = 0; k < 8; k++) v[k] = __ldcs(src + (size_t)k * HW);

    __half2 h0 = __floats2half2_rn(v[0], v[1]);
    __half2 h1 = __floats2half2_rn(v[2], v[3]);
    __half2 h2 = __floats2half2_rn(v[4], v[5]);
    __half2 h3 = __floats2half2_rn(v[6], v[7]);
    uint4 o;
    o.x = *reinterpret_cast<unsigned*>(&h0);
    o.y = *reinterpret_cast<unsigned*>(&h1);
    o.z = *reinterpret_cast<unsigned*>(&h2);
    o.w = *reinterpret_cast<unsigned*>(&h3);
    reinterpret_cast<uint4*>(timg)[t] = o;
}

// ---------------------------------------------------------------------------
// Gather (proven path): 2 threads per pixel (8 channels each), branchless
// corners, 4 unconditional LDG.128 on timg (default policy -> L2 hits when
// pipelined), streaming stores on out.
//   x = (i-1) + flow_ch0 * 0.5*(W-1)   (width coord)
//   y = (j-1) + flow_ch1 * 0.5*(H-1)   (height coord)
// ---------------------------------------------------------------------------
template <unsigned LG>
__device__ __forceinline__ void do_gather(const float* __restrict__ flow,
                                          const __half* __restrict__ timg,
                                          float* __restrict__ outp,
                                          unsigned bx) {
    const unsigned t     = bx * 256u + threadIdx.x;
    const unsigned chalf = t & 1u;
    const unsigned p     = t >> 1;
    constexpr unsigned W  = 1u << LG;
    constexpr unsigned HW = 1u << (2u * LG);
    constexpr int      Wi = (int)W;
    const unsigned j   = p & (W - 1u);
    const unsigned i   = (p >> LG) & (W - 1u);
    const unsigned b   = p >> (2u * LG);
    const unsigned pix = p & (HW - 1u);

    const float f0 = __ldcs(flow + (size_t)(b * 2u) * HW + pix);
    const float f1 = __ldcs(flow + (size_t)(b * 2u + 1u) * HW + pix);

    constexpr float sc = 0.5f * (float)(W - 1u);
    const float x = (float)((int)i - 1) + f0 * sc;   // width coord
    const float y = (float)((int)j - 1) + f1 * sc;   // height coord

    const float x0f = floorf(x);
    const float y0f = floorf(y);
    const int x0 = (int)x0f, x1 = x0 + 1;
    const int y0 = (int)y0f, y1 = y0 + 1;
    const float fx = x - x0f, fy = y - y0f;

    const float wx1 = (x1 >= 0 && x1 < Wi) ? fx        : 0.0f;
    const float wx0 = (x0 >= 0 && x0 < Wi) ? 1.0f - fx : 0.0f;
    const float wy1 = (y1 >= 0 && y1 < Wi) ? fy        : 0.0f;
    const float wy0 = (y0 >= 0 && y0 < Wi) ? 1.0f - fy : 0.0f;

    const unsigned x0c = (unsigned)min(max(x0, 0), Wi - 1);
    const unsigned x1c = (unsigned)min(max(x1, 0), Wi - 1);
    const unsigned y0c = (unsigned)min(max(y0, 0), Wi - 1);
    const unsigned y1c = (unsigned)min(max(y1, 0), Wi - 1);

    const uint4* base = reinterpret_cast<const uint4*>(timg)
                        + (size_t)(b * HW) * 2u + chalf;
    const uint4 r00 = __ldg(base + (size_t)(y0c * W + x0c) * 2u);
    const uint4 r01 = __ldg(base + (size_t)(y0c * W + x1c) * 2u);
    const uint4 r10 = __ldg(base + (size_t)(y1c * W + x0c) * 2u);
    const uint4 r11 = __ldg(base + (size_t)(y1c * W + x1c) * 2u);

    const float w00 = wy0 * wx0, w01 = wy0 * wx1;
    const float w10 = wy1 * wx0, w11 = wy1 * wx1;

    float acc[8];
    const unsigned c00[4] = {r00.x, r00.y, r00.z, r00.w};
    const unsigned c01[4] = {r01.x, r01.y, r01.z, r01.w};
    const unsigned c10[4] = {r10.x, r10.y, r10.z, r10.w};
    const unsigned c11[4] = {r11.x, r11.y, r11.z, r11.w};
#pragma unroll
    for (int q = 0; q < 4; q++) {
        float2 v00 = __half22float2(*reinterpret_cast<const __half2*>(&c00[q]));
        float2 v01 = __half22float2(*reinterpret_cast<const __half2*>(&c01[q]));
        float2 v10 = __half22float2(*reinterpret_cast<const __half2*>(&c10[q]));
        float2 v11 = __half22float2(*reinterpret_cast<const __half2*>(&c11[q]));
        acc[2 * q + 0] = w00 * v00.x + w01 * v01.x + w10 * v10.x + w11 * v11.x;
        acc[2 * q + 1] = w00 * v00.y + w01 * v01.y + w10 * v10.y + w11 * v11.y;
    }

    float* ob = outp + (size_t)(b * 16u + chalf * 8u) * HW + pix;
#pragma unroll
    for (int q = 0; q < 8; q++) {
        __stcs(ob + (size_t)q * HW, acc[q]);
    }
}

// Small-scale dispatchers (10752 blocks: s256 [0,8192) | s128 [8192,10240) |
// s64 [10240,10752)).
__device__ __forceinline__ void tsmall(unsigned bx,
                                       const float* im1, const float* im2,
                                       const float* im3) {
    if (bx < 8192u)       do_transpose<8>(im1, g_timg + 67108864u, bx);
    else if (bx < 10240u) do_transpose<7>(im2, g_timg + 83886080u, bx - 8192u);
    else                  do_transpose<6>(im3, g_timg + 88080384u, bx - 10240u);
}
__device__ __forceinline__ void gsmall(unsigned bx,
                                       const float* fl1, const float* fl2,
                                       const float* fl3, float* out) {
    if (bx < 8192u)       do_gather<8>(fl1, g_timg + 67108864u, out + 67108864u, bx);
    else if (bx < 10240u) do_gather<7>(fl2, g_timg + 83886080u, out + 83886080u, bx - 8192u);
    else                  do_gather<6>(fl3, g_timg + 88080384u, out + 88080384u, bx - 10240u);
}

// ---------------------------------------------------------------------------
// kA: T512 batch pair 0 (blocks [0,4096)) + all small transposes. Grid 14848.
// ---------------------------------------------------------------------------
__global__ void kA(const float* __restrict__ im0, const float* __restrict__ im1,
                   const float* __restrict__ im2, const float* __restrict__ im3) {
    const unsigned bx = blockIdx.x;
    if (bx < 4096u) do_transpose<9>(im0, g_timg, bx);
    else            tsmall(bx - 4096u, im1, im2, im3);
}

// ---------------------------------------------------------------------------
// kB (phase i = 0..6): G512 pair i (4096) || T512 pair i+1 (4096) || small
// gathers chunk i (1536). 19-block groups, lanes 0-7 G / 8-15 T / 16-18 Gs.
// Grid = 512*19 = 9728. Gather of pair i reads timg written one launch ago
// (pair footprint 16.8 MB << L2) -> L2 hits instead of DRAM re-reads.
// ---------------------------------------------------------------------------
__global__ void kB(const float* __restrict__ im0, const float* __restrict__ fl0,
                   const float* __restrict__ fl1, const float* __restrict__ fl2,
                   const float* __restrict__ fl3, float* __restrict__ out,
                   unsigned phase) {
    const unsigned bx   = blockIdx.x;
    const unsigned grp  = bx / 19u;
    const unsigned lane = bx - grp * 19u;
    if (lane < 8u) {
        do_gather<9>(fl0, g_timg, out, phase * 4096u + grp * 8u + lane);
    } else if (lane < 16u) {
        do_transpose<9>(im0, g_timg, (phase + 1u) * 4096u + grp * 8u + (lane - 8u));
    } else {
        gsmall(phase * 1536u + grp * 3u + (lane - 16u), fl1, fl2, fl3, out);
    }
}

// ---------------------------------------------------------------------------
// kC: G512 pair 7 (blocks [28672, 32768)). Grid 4096.
// ---------------------------------------------------------------------------
__global__ void kC(const float* __restrict__ fl0, float* __restrict__ out) {
    do_gather<9>(fl0, g_timg, out, 28672u + blockIdx.x);
}

// ---------------------------------------------------------------------------
// Inputs (metadata order): img0, flow0, img1, flow1, img2, flow2, img3, flow3.
// ---------------------------------------------------------------------------
extern "C" void kernel_launch(void* const* d_in, const int* in_sizes, int n_in,
                              void* d_out, int out_size) {
    (void)in_sizes; (void)n_in; (void)out_size;
    const float* im0 = (const float*)d_in[0];
    const float* fl0 = (const float*)d_in[1];
    const float* im1 = (const float*)d_in[2];
    const float* fl1 = (const float*)d_in[3];
    const float* im2 = (const float*)d_in[4];
    const float* fl2 = (const float*)d_in[5];
    const float* im3 = (const float*)d_in[6];
    const float* fl3 = (const float*)d_in[7];
    float* out = (float*)d_out;

    kA<<<14848, 256>>>(im0, im1, im2, im3);
    for (unsigned i = 0; i < 7; i++)
        kB<<<9728, 256>>>(im0, fl0, fl1, fl2, fl3, out, i);
    kC<<<4096, 256>>>(fl0, out);
}

// round 8
// speedup vs baseline: 1.0517x; 1.0517x over previous
#include <cuda_runtime.h>
#include <cuda_fp16.h>

// Channel-last fp16 copies of all 4 img tensors.
// Half-element offsets: s512: 0 | s256: 67,108,864 | s128: 83,886,080 |
// s64: 88,080,384. Total 89,128,960 halfs.
__device__ __half g_timg[89128960];

// ---------------------------------------------------------------------------
// Transpose [B,C,H,W] fp32 -> [B,H,W,C] fp16 (unchanged from R5). Thread t ->
// (pixel p=t>>1, channel group g=t&1): 8 strided coalesced LDG.32 (streaming),
// one coalesced STG.128 (default policy -> L2-resident for the gather).
// ---------------------------------------------------------------------------
template <unsigned LG>
__device__ __forceinline__ void do_transpose(const float* __restrict__ img,
                                             __half* __restrict__ timg,
                                             unsigned bx) {
    const unsigned t  = bx * 256u + threadIdx.x;
    const unsigned g  = t & 1u;
    const unsigned p  = t >> 1;
    constexpr unsigned HW = 1u << (2u * LG);
    const unsigned b  = p >> (2u * LG);

    const float* src = img + (size_t)p + (size_t)(b * 15u + g * 8u) * HW;
    float v[8];
#pragma unroll
    for (int k = 0; k < 8; k++) v[k] = __ldcs(src + (size_t)k * HW);

    __half2 h0 = __floats2half2_rn(v[0], v[1]);
    __half2 h1 = __floats2half2_rn(v[2], v[3]);
    __half2 h2 = __floats2half2_rn(v[4], v[5]);
    __half2 h3 = __floats2half2_rn(v[6], v[7]);
    uint4 o;
    o.x = *reinterpret_cast<unsigned*>(&h0);
    o.y = *reinterpret_cast<unsigned*>(&h1);
    o.z = *reinterpret_cast<unsigned*>(&h2);
    o.w = *reinterpret_cast<unsigned*>(&h3);
    reinterpret_cast<uint4*>(timg)[t] = o;
}

// ---------------------------------------------------------------------------
// Gather, 2 PIXELS PER THREAD (8 channels each): all 10 loads (2 flow + 8
// corner LDG.128) issued before any consumption -> MLP ~8-10 per thread.
// Branchless corners: validity folded into weights, clamped indices.
// Block covers pixels [bxx*256, bxx*256+256): thread handles l and l+128.
//   x = (i-1) + flow_ch0 * 0.5*(W-1)   (width coord)
//   y = (j-1) + flow_ch1 * 0.5*(H-1)   (height coord)
// ---------------------------------------------------------------------------
template <unsigned LG>
__device__ __forceinline__ void do_gather2(const float* __restrict__ flow,
                                           const __half* __restrict__ timg,
                                           float* __restrict__ outp,
                                           unsigned bxx) {
    const unsigned tid   = threadIdx.x;
    const unsigned chalf = tid & 1u;
    const unsigned l     = tid >> 1;
    constexpr unsigned W  = 1u << LG;
    constexpr unsigned HW = 1u << (2u * LG);
    constexpr int      Wi = (int)W;
    constexpr float    sc = 0.5f * (float)(W - 1u);

    unsigned pp[2];
    pp[0] = bxx * 256u + l;
    pp[1] = pp[0] + 128u;

    // flow loads for both pixels first
    float f0[2], f1[2];
    unsigned bb[2], pix[2];
#pragma unroll
    for (int e = 0; e < 2; e++) {
        bb[e]  = pp[e] >> (2u * LG);
        pix[e] = pp[e] & (HW - 1u);
        f0[e] = __ldcs(flow + (size_t)(bb[e] * 2u) * HW + pix[e]);
        f1[e] = __ldcs(flow + (size_t)(bb[e] * 2u + 1u) * HW + pix[e]);
    }

    float w00[2], w01[2], w10[2], w11[2];
    const uint4* ad[2][4];
#pragma unroll
    for (int e = 0; e < 2; e++) {
        const unsigned j = pp[e] & (W - 1u);
        const unsigned i = (pp[e] >> LG) & (W - 1u);

        const float x = (float)((int)i - 1) + f0[e] * sc;   // width coord
        const float y = (float)((int)j - 1) + f1[e] * sc;   // height coord

        const float x0f = floorf(x);
        const float y0f = floorf(y);
        const int x0 = (int)x0f, x1 = x0 + 1;
        const int y0 = (int)y0f, y1 = y0 + 1;
        const float fx = x - x0f, fy = y - y0f;

        const float wx1 = (x1 >= 0 && x1 < Wi) ? fx        : 0.0f;
        const float wx0 = (x0 >= 0 && x0 < Wi) ? 1.0f - fx : 0.0f;
        const float wy1 = (y1 >= 0 && y1 < Wi) ? fy        : 0.0f;
        const float wy0 = (y0 >= 0 && y0 < Wi) ? 1.0f - fy : 0.0f;

        const unsigned x0c = (unsigned)min(max(x0, 0), Wi - 1);
        const unsigned x1c = (unsigned)min(max(x1, 0), Wi - 1);
        const unsigned y0c = (unsigned)min(max(y0, 0), Wi - 1);
        const unsigned y1c = (unsigned)min(max(y1, 0), Wi - 1);

        w00[e] = wy0 * wx0; w01[e] = wy0 * wx1;
        w10[e] = wy1 * wx0; w11[e] = wy1 * wx1;

        const uint4* base = reinterpret_cast<const uint4*>(timg)
                            + (size_t)(bb[e] * HW) * 2u + chalf;
        ad[e][0] = base + (size_t)(y0c * W + x0c) * 2u;
        ad[e][1] = base + (size_t)(y0c * W + x1c) * 2u;
        ad[e][2] = base + (size_t)(y1c * W + x0c) * 2u;
        ad[e][3] = base + (size_t)(y1c * W + x1c) * 2u;
    }

    // all 8 corner loads in flight
    uint4 r[2][4];
#pragma unroll
    for (int e = 0; e < 2; e++)
#pragma unroll
        for (int k = 0; k < 4; k++) r[e][k] = __ldg(ad[e][k]);

#pragma unroll
    for (int e = 0; e < 2; e++) {
        float acc[8];
        const unsigned c00[4] = {r[e][0].x, r[e][0].y, r[e][0].z, r[e][0].w};
        const unsigned c01[4] = {r[e][1].x, r[e][1].y, r[e][1].z, r[e][1].w};
        const unsigned c10[4] = {r[e][2].x, r[e][2].y, r[e][2].z, r[e][2].w};
        const unsigned c11[4] = {r[e][3].x, r[e][3].y, r[e][3].z, r[e][3].w};
#pragma unroll
        for (int q = 0; q < 4; q++) {
            float2 v00 = __half22float2(*reinterpret_cast<const __half2*>(&c00[q]));
            float2 v01 = __half22float2(*reinterpret_cast<const __half2*>(&c01[q]));
            float2 v10 = __half22float2(*reinterpret_cast<const __half2*>(&c10[q]));
            float2 v11 = __half22float2(*reinterpret_cast<const __half2*>(&c11[q]));
            acc[2 * q + 0] = w00[e] * v00.x + w01[e] * v01.x
                           + w10[e] * v10.x + w11[e] * v11.x;
            acc[2 * q + 1] = w00[e] * v00.y + w01[e] * v01.y
                           + w10[e] * v10.y + w11[e] * v11.y;
        }
        float* ob = outp + (size_t)(bb[e] * 16u + chalf * 8u) * HW + pix[e];
#pragma unroll
        for (int q = 0; q < 8; q++) {
            __stcs(ob + (size_t)q * HW, acc[q]);
        }
    }
}

// Small-scale dispatchers.
// Transpose blocks (128 px): s256 [0,8192) | s128 [8192,10240) | s64 [10240,10752).
__device__ __forceinline__ void tsmall(unsigned bx,
                                       const float* im1, const float* im2,
                                       const float* im3) {
    if (bx < 8192u)       do_transpose<8>(im1, g_timg + 67108864u, bx);
    else if (bx < 10240u) do_transpose<7>(im2, g_timg + 83886080u, bx - 8192u);
    else                  do_transpose<6>(im3, g_timg + 88080384u, bx - 10240u);
}
// Gather2 blocks (256 px): s256 [0,4096) | s128 [4096,5120) | s64 [5120,5376).
__device__ __forceinline__ void gsmall2(unsigned bx,
                                        const float* fl1, const float* fl2,
                                        const float* fl3, float* out) {
    if (bx < 4096u)      do_gather2<8>(fl1, g_timg + 67108864u, out + 67108864u, bx);
    else if (bx < 5120u) do_gather2<7>(fl2, g_timg + 83886080u, out + 83886080u, bx - 4096u);
    else                 do_gather2<6>(fl3, g_timg + 88080384u, out + 88080384u, bx - 5120u);
}

// ---------------------------------------------------------------------------
// K1: T512 all 16 batches, ascending (32768 blocks) -> late batches L2-hot.
// ---------------------------------------------------------------------------
__global__ void k1_transpose512(const float* __restrict__ im0) {
    do_transpose<9>(im0, g_timg, blockIdx.x);
}

// ---------------------------------------------------------------------------
// K2: G512 (16384 gather2 blocks, DESCENDING batch: batch 15 first -> reads
// k1's most-recent timg writes from L2) interleaved 3:2 with small-scale
// transposes (10752). Groups of 5: lanes 0-2 gather, 3-4 transpose.
// Grid = 5462*5 = 27310.
// ---------------------------------------------------------------------------
__global__ void k2_mixed(const float* __restrict__ fl0,
                         const float* __restrict__ im1,
                         const float* __restrict__ im2,
                         const float* __restrict__ im3,
                         float* __restrict__ out) {
    const unsigned bx   = blockIdx.x;
    const unsigned grp  = bx / 5u;
    const unsigned lane = bx - grp * 5u;
    if (lane < 3u) {
        const unsigned g = grp * 3u + lane;
        if (g < 16384u) {
            // descending batch order: 1024 blocks per batch
            const unsigned bb  = 15u - (g >> 10);
            const unsigned blk = g & 1023u;
            do_gather2<9>(fl0, g_timg, out, bb * 1024u + blk);
        }
        return;
    }
    const unsigned ti = grp * 2u + (lane - 3u);
    if (ti < 10752u) tsmall(ti, im1, im2, im3);
}

// ---------------------------------------------------------------------------
// K3: small-scale gathers (5376 gather2 blocks).
// ---------------------------------------------------------------------------
__global__ void k3_gather_small(const float* __restrict__ fl1,
                                const float* __restrict__ fl2,
                                const float* __restrict__ fl3,
                                float* __restrict__ out) {
    gsmall2(blockIdx.x, fl1, fl2, fl3, out);
}

// ---------------------------------------------------------------------------
// Inputs (metadata order): img0, flow0, img1, flow1, img2, flow2, img3, flow3.
// ---------------------------------------------------------------------------
extern "C" void kernel_launch(void* const* d_in, const int* in_sizes, int n_in,
                              void* d_out, int out_size) {
    (void)in_sizes; (void)n_in; (void)out_size;
    const float* im0 = (const float*)d_in[0];
    const float* fl0 = (const float*)d_in[1];
    const float* im1 = (const float*)d_in[2];
    const float* fl1 = (const float*)d_in[3];
    const float* im2 = (const float*)d_in[4];
    const float* fl2 = (const float*)d_in[5];
    const float* im3 = (const float*)d_in[6];
    const float* fl3 = (const float*)d_in[7];
    float* out = (float*)d_out;

    k1_transpose512<<<32768, 256>>>(im0);
    k2_mixed<<<27310, 256>>>(fl0, im1, im2, im3, out);
    k3_gather_small<<<5376, 256>>>(fl1, fl2, fl3, out);
}